// round 1
// baseline (speedup 1.0000x reference)
#include <cuda_runtime.h>

#define HID 64
#define TAB 16384
#define XMIN (-10.0f)
#define XMAX (10.0f)
#define MAXN 100000

// Scratch (allocation-free rule: device globals)
__device__ float g_agg[MAXN * HID];      // 25.6 MB segment-sum accumulator
__device__ float g_tab[TAB * HID];       // 4 MB lookup table of edge-MLP f(x)

__device__ __forceinline__ float silu_f(float v) { return v / (1.0f + __expf(-v)); }

// ---------------------------------------------------------------------------
// Kernel 1: zero the aggregation buffer (float4 stores)
// ---------------------------------------------------------------------------
__global__ __launch_bounds__(256) void zero_agg_kernel(int n4) {
    int i = blockIdx.x * blockDim.x + threadIdx.x;
    if (i < n4) reinterpret_cast<float4*>(g_agg)[i] = make_float4(0.f, 0.f, 0.f, 0.f);
}

// ---------------------------------------------------------------------------
// Kernel 2: build lookup table  f(x) = silu(silu(x*W1+b1) @ W2 + b2)
// 64 threads/block, 16 table rows per block. W2 staged in smem.
// ---------------------------------------------------------------------------
__global__ __launch_bounds__(64) void build_table_kernel(
    const float* __restrict__ W1, const float* __restrict__ b1,
    const float* __restrict__ W2, const float* __restrict__ b2)
{
    __shared__ float sW2[HID * HID];
    __shared__ float s1[HID];
    int h = threadIdx.x;
    for (int idx = h; idx < HID * HID; idx += 64) sW2[idx] = W2[idx];
    float w1 = W1[h], bb1 = b1[h], bb2 = b2[h];
    __syncthreads();

    for (int r = 0; r < 16; r++) {
        int i = blockIdx.x * 16 + r;
        float x = XMIN + (XMAX - XMIN) * ((float)i / (float)(TAB - 1));
        s1[h] = silu_f(fmaf(x, w1, bb1));
        __syncthreads();
        float acc = bb2;
#pragma unroll 16
        for (int k = 0; k < HID; k++) acc = fmaf(s1[k], sW2[k * HID + h], acc);
        g_tab[i * HID + h] = silu_f(acc);
        __syncthreads();
    }
}

// ---------------------------------------------------------------------------
// Kernel 3: per-edge lerp + scatter-add.
// 16 threads per edge; each thread handles 4 contiguous features:
//   2x LDG.128 from adjacent table rows, lerp, 1x red.global.add.v4.f32
// ---------------------------------------------------------------------------
__global__ __launch_bounds__(256) void edge_kernel(
    const int* __restrict__ row,          // edge_index[0][*], length E
    const float* __restrict__ xattr,      // edge_attr, length E
    int E)
{
    int gid = blockIdx.x * blockDim.x + threadIdx.x;
    int e = gid >> 4;
    if (e >= E) return;
    int t = gid & 15;

    float x = __ldg(xattr + e);
    float tf = (x - XMIN) * ((float)(TAB - 1) / (XMAX - XMIN));
    tf = fminf(fmaxf(tf, 0.0f), (float)(TAB - 1));
    int i = (int)tf;
    if (i > TAB - 2) i = TAB - 2;
    float fr = tf - (float)i;

    const float4* p0 = reinterpret_cast<const float4*>(g_tab + (size_t)i * HID) + t;
    float4 a = __ldg(p0);
    float4 b = __ldg(p0 + HID / 4);
    float4 v;
    v.x = fmaf(fr, b.x - a.x, a.x);
    v.y = fmaf(fr, b.y - a.y, a.y);
    v.z = fmaf(fr, b.z - a.z, a.z);
    v.w = fmaf(fr, b.w - a.w, a.w);

    int r = __ldg(row + e);
    float* dst = g_agg + (size_t)r * HID + t * 4;
    asm volatile("red.global.add.v4.f32 [%0], {%1, %2, %3, %4};"
                 :: "l"(dst), "f"(v.x), "f"(v.y), "f"(v.z), "f"(v.w)
                 : "memory");
}

// ---------------------------------------------------------------------------
// Kernel 4: node MLP  out = silu(agg @ W3 + b3) @ W4 + b4
// Thread-per-node, fused two layers; W3 transposed + W4 staged in smem,
// float4 broadcast weight loads (uniform smem address across the warp).
// ---------------------------------------------------------------------------
__global__ __launch_bounds__(128) void node_kernel(
    const float* __restrict__ W3, const float* __restrict__ b3,
    const float* __restrict__ W4, const float* __restrict__ b4,
    float* __restrict__ out, int N)
{
    __shared__ float sW3t[HID * HID];   // [h][k] (transposed)
    __shared__ float sW4[HID * HID];    // [hm][ho] (as stored)
    __shared__ float sb3[HID];
    __shared__ float sb4[HID];

    for (int idx = threadIdx.x; idx < HID * HID; idx += 128) {
        int k = idx >> 6, h = idx & 63;
        sW3t[h * HID + k] = W3[idx];
        sW4[idx] = W4[idx];
    }
    if (threadIdx.x < HID) {
        sb3[threadIdx.x] = b3[threadIdx.x];
        sb4[threadIdx.x] = b4[threadIdx.x];
    }
    __syncthreads();

    int node = blockIdx.x * 128 + threadIdx.x;
    if (node >= N) return;

    float in[HID];
    const float4* src = reinterpret_cast<const float4*>(g_agg + (size_t)node * HID);
#pragma unroll
    for (int j = 0; j < HID / 4; j++) {
        float4 v = src[j];
        in[4 * j] = v.x; in[4 * j + 1] = v.y; in[4 * j + 2] = v.z; in[4 * j + 3] = v.w;
    }

    float acc[HID];
#pragma unroll
    for (int j = 0; j < HID; j++) acc[j] = sb4[j];

    for (int hm = 0; hm < HID; hm++) {
        const float4* wrow = reinterpret_cast<const float4*>(sW3t + hm * HID);
        float d0 = 0.f, d1 = 0.f, d2 = 0.f, d3 = 0.f;
#pragma unroll
        for (int j = 0; j < HID / 4; j++) {
            float4 w = wrow[j];
            d0 = fmaf(in[4 * j],     w.x, d0);
            d1 = fmaf(in[4 * j + 1], w.y, d1);
            d2 = fmaf(in[4 * j + 2], w.z, d2);
            d3 = fmaf(in[4 * j + 3], w.w, d3);
        }
        float m = silu_f(((d0 + d1) + (d2 + d3)) + sb3[hm]);

        const float4* w4row = reinterpret_cast<const float4*>(sW4 + hm * HID);
#pragma unroll
        for (int j = 0; j < HID / 4; j++) {
            float4 w = w4row[j];
            acc[4 * j]     = fmaf(m, w.x, acc[4 * j]);
            acc[4 * j + 1] = fmaf(m, w.y, acc[4 * j + 1]);
            acc[4 * j + 2] = fmaf(m, w.z, acc[4 * j + 2]);
            acc[4 * j + 3] = fmaf(m, w.w, acc[4 * j + 3]);
        }
    }

    float4* dst = reinterpret_cast<float4*>(out + (size_t)node * HID);
#pragma unroll
    for (int j = 0; j < HID / 4; j++)
        dst[j] = make_float4(acc[4 * j], acc[4 * j + 1], acc[4 * j + 2], acc[4 * j + 3]);
}

// ---------------------------------------------------------------------------
// Launch
// ---------------------------------------------------------------------------
extern "C" void kernel_launch(void* const* d_in, const int* in_sizes, int n_in,
                              void* d_out, int out_size)
{
    const int*   edge_index = (const int*)d_in[0];   // [2, E]
    const float* edge_attr  = (const float*)d_in[1]; // [E, 1]
    const float* W1 = (const float*)d_in[2];
    const float* b1 = (const float*)d_in[3];
    const float* W2 = (const float*)d_in[4];
    const float* b2 = (const float*)d_in[5];
    const float* W3 = (const float*)d_in[6];
    const float* b3 = (const float*)d_in[7];
    const float* W4 = (const float*)d_in[8];
    const float* b4 = (const float*)d_in[9];
    float* out = (float*)d_out;

    int E = in_sizes[1];           // edge_attr has E*1 elements
    int N = out_size / HID;        // output is [N, 64]

    int n4 = N * HID / 4;
    zero_agg_kernel<<<(n4 + 255) / 256, 256>>>(n4);
    build_table_kernel<<<TAB / 16, 64>>>(W1, b1, W2, b2);

    int egrid = (int)(((long long)E * 16 + 255) / 256);
    edge_kernel<<<egrid, 256>>>(edge_index, edge_attr, E);

    node_kernel<<<(N + 127) / 128, 128>>>(W3, b3, W4, b4, out, N);
}